// round 2
// baseline (speedup 1.0000x reference)
#include <cuda_runtime.h>

#define NN 50000
#define EE 800000
#define DH 64

// ---- scratch (device globals; no allocation allowed) ----
__device__ float g_h[NN * DH];
__device__ float g_P[NN * DH];
__device__ float g_Q[NN * DH];
__device__ float g_agg[NN * DH];

// =====================================================================
// Input projection: h = x @ in_w + in_b   ([N,3] @ [3,64])
// =====================================================================
__global__ void k_input(const float* __restrict__ x, const float* __restrict__ w,
                        const float* __restrict__ b, int n) {
    int t = blockIdx.x * blockDim.x + threadIdx.x;
    if (t >= n * DH) return;
    int i = t / DH, j = t % DH;
    float x0 = x[i * 3 + 0], x1 = x[i * 3 + 1], x2 = x[i * 3 + 2];
    g_h[t] = x0 * w[0 * DH + j] + x1 * w[1 * DH + j] + x2 * w[2 * DH + j] + b[j];
}

// =====================================================================
// Zero the aggregation buffer
// =====================================================================
__global__ void k_zero_agg() {
    int t = blockIdx.x * blockDim.x + threadIdx.x;
    if (t < NN * DH) g_agg[t] = 0.f;
}

// =====================================================================
// P = h @ W1[:64], Q = h @ W1[64:]   (dual GEMM, no bias)
// 256 threads, tile 128 rows x 64 cols, 8x4 micro-tile
// smem: As[128*64] + Ws[64*64] = 48KB
// =====================================================================
__global__ void k_pq(const float* __restrict__ w1, int n) {
    extern __shared__ float sm[];
    float* As = sm;             // [128][64]
    float* Ws = sm + 128 * DH;  // [64][64]
    int t = threadIdx.x;
    int base = blockIdx.x * 128;

    // stage A (h tile), coalesced float4
    #pragma unroll
    for (int it = 0; it < 8; it++) {
        int q = it * 256 + t;
        int i = q >> 4, j4 = (q & 15) * 4;
        float4 v = make_float4(0.f, 0.f, 0.f, 0.f);
        if (base + i < n) v = *(const float4*)&g_h[(base + i) * DH + j4];
        *(float4*)&As[i * DH + j4] = v;
    }

    int tx = t & 15, ty = t >> 4;
    int j0 = tx * 4, i0 = ty * 8;

    for (int pass = 0; pass < 2; pass++) {
        __syncthreads();
        const float* wsrc = w1 + pass * 64 * DH;
        #pragma unroll
        for (int it = 0; it < 4; it++) {
            int q = it * 256 + t;
            int k = q >> 4, j4 = (q & 15) * 4;
            *(float4*)&Ws[k * DH + j4] = *(const float4*)&wsrc[k * DH + j4];
        }
        __syncthreads();

        float acc[8][4];
        #pragma unroll
        for (int r = 0; r < 8; r++)
            #pragma unroll
            for (int c = 0; c < 4; c++) acc[r][c] = 0.f;

        #pragma unroll 4
        for (int k = 0; k < 64; k++) {
            float4 w = *(const float4*)&Ws[k * DH + j0];
            #pragma unroll
            for (int r = 0; r < 8; r++) {
                float a = As[(i0 + r) * DH + k];
                acc[r][0] += a * w.x; acc[r][1] += a * w.y;
                acc[r][2] += a * w.z; acc[r][3] += a * w.w;
            }
        }

        float* dst = (pass == 0) ? g_P : g_Q;
        #pragma unroll
        for (int r = 0; r < 8; r++) {
            int i = base + i0 + r;
            if (i < n)
                *(float4*)&dst[i * DH + j0] =
                    make_float4(acc[r][0], acc[r][1], acc[r][2], acc[r][3]);
        }
    }
}

// =====================================================================
// Edge kernel (dominant): hid = relu(P[row] + Q[col] + b1);
//                         m = hid @ W2 + b2; atomicAdd into agg[col]
// 256 threads, 128 edges/block. smem ~50KB (needs attribute)
// =====================================================================
__global__ void k_edge(const int* __restrict__ row, const int* __restrict__ col,
                       const float* __restrict__ b1, const float* __restrict__ w2,
                       const float* __restrict__ b2, int e_total) {
    extern __shared__ float sm[];
    float* hid = sm;                 // [128][64]
    float* Ws  = sm + 128 * DH;      // [64][64]
    float* b2s = Ws + 64 * DH;       // [64]
    float* b1s = b2s + 64;           // [64]
    int*   cls = (int*)(b1s + 64);   // [128]
    int t = threadIdx.x;
    int base = blockIdx.x * 128;

    if (t < 64) { b2s[t] = b2[t]; b1s[t] = b1[t]; }
    if (t < 128) cls[t] = (base + t < e_total) ? col[base + t] : 0;

    // load W2
    #pragma unroll
    for (int it = 0; it < 4; it++) {
        int q = it * 256 + t;
        int k = q >> 4, j4 = (q & 15) * 4;
        *(float4*)&Ws[k * DH + j4] = *(const float4*)&w2[k * DH + j4];
    }
    __syncthreads();

    // stage 1: gather + add + bias + relu -> hid
    #pragma unroll
    for (int it = 0; it < 8; it++) {
        int q = it * 256 + t;
        int e = q >> 4, j4 = (q & 15) * 4;
        int ge = base + e;
        float4 hv = make_float4(0.f, 0.f, 0.f, 0.f);
        if (ge < e_total) {
            int rr = row[ge], cc = col[ge];
            float4 p  = *(const float4*)&g_P[rr * DH + j4];
            float4 qv = *(const float4*)&g_Q[cc * DH + j4];
            hv.x = fmaxf(p.x + qv.x + b1s[j4 + 0], 0.f);
            hv.y = fmaxf(p.y + qv.y + b1s[j4 + 1], 0.f);
            hv.z = fmaxf(p.z + qv.z + b1s[j4 + 2], 0.f);
            hv.w = fmaxf(p.w + qv.w + b1s[j4 + 3], 0.f);
        }
        *(float4*)&hid[e * DH + j4] = hv;
    }
    __syncthreads();

    int tx = t & 15, ty = t >> 4;
    int j0 = tx * 4, e0 = ty * 8;
    float acc[8][4];
    #pragma unroll
    for (int r = 0; r < 8; r++) {
        acc[r][0] = b2s[j0 + 0]; acc[r][1] = b2s[j0 + 1];
        acc[r][2] = b2s[j0 + 2]; acc[r][3] = b2s[j0 + 3];
    }

    #pragma unroll 4
    for (int k = 0; k < 64; k++) {
        float4 w = *(const float4*)&Ws[k * DH + j0];
        #pragma unroll
        for (int r = 0; r < 8; r++) {
            float a = hid[(e0 + r) * DH + k];
            acc[r][0] += a * w.x; acc[r][1] += a * w.y;
            acc[r][2] += a * w.z; acc[r][3] += a * w.w;
        }
    }

    // scatter-add
    #pragma unroll
    for (int r = 0; r < 8; r++) {
        int ge = base + e0 + r;
        if (ge < e_total) {
            float* dst = &g_agg[cls[e0 + r] * DH + j0];
            atomicAdd(dst + 0, acc[r][0]);
            atomicAdd(dst + 1, acc[r][1]);
            atomicAdd(dst + 2, acc[r][2]);
            atomicAdd(dst + 3, acc[r][3]);
        }
    }
}

// =====================================================================
// Node update: h = relu( relu(h@U1a + agg@U1b + b1) @ U2 + b2 )   (in place)
// =====================================================================
__global__ void k_update(const float* __restrict__ u1, const float* __restrict__ ub1,
                         const float* __restrict__ u2, const float* __restrict__ ub2,
                         int n) {
    extern __shared__ float sm[];
    float* As  = sm;             // [128][64]
    float* Ws  = sm + 128 * DH;  // [64][64]
    float* b1s = Ws + 64 * DH;
    float* b2s = b1s + 64;
    int t = threadIdx.x;
    int base = blockIdx.x * 128;
    if (t < 64) { b1s[t] = ub1[t]; b2s[t] = ub2[t]; }

    int tx = t & 15, ty = t >> 4;
    int j0 = tx * 4, i0 = ty * 8;

    float acc[8][4];
    #pragma unroll
    for (int r = 0; r < 8; r++)
        #pragma unroll
        for (int c = 0; c < 4; c++) acc[r][c] = 0.f;

    for (int pass = 0; pass < 2; pass++) {
        __syncthreads();
        const float* a_src = (pass == 0) ? g_h : g_agg;
        #pragma unroll
        for (int it = 0; it < 8; it++) {
            int q = it * 256 + t;
            int i = q >> 4, j4 = (q & 15) * 4;
            float4 v = make_float4(0.f, 0.f, 0.f, 0.f);
            if (base + i < n) v = *(const float4*)&a_src[(base + i) * DH + j4];
            *(float4*)&As[i * DH + j4] = v;
        }
        const float* wsrc = u1 + pass * 64 * DH;
        #pragma unroll
        for (int it = 0; it < 4; it++) {
            int q = it * 256 + t;
            int k = q >> 4, j4 = (q & 15) * 4;
            *(float4*)&Ws[k * DH + j4] = *(const float4*)&wsrc[k * DH + j4];
        }
        __syncthreads();
        #pragma unroll 4
        for (int k = 0; k < 64; k++) {
            float4 w = *(const float4*)&Ws[k * DH + j0];
            #pragma unroll
            for (int r = 0; r < 8; r++) {
                float a = As[(i0 + r) * DH + k];
                acc[r][0] += a * w.x; acc[r][1] += a * w.y;
                acc[r][2] += a * w.z; acc[r][3] += a * w.w;
            }
        }
    }
    __syncthreads();

    // hid = relu(acc + b1) -> As
    #pragma unroll
    for (int r = 0; r < 8; r++) {
        float4 hv;
        hv.x = fmaxf(acc[r][0] + b1s[j0 + 0], 0.f);
        hv.y = fmaxf(acc[r][1] + b1s[j0 + 1], 0.f);
        hv.z = fmaxf(acc[r][2] + b1s[j0 + 2], 0.f);
        hv.w = fmaxf(acc[r][3] + b1s[j0 + 3], 0.f);
        *(float4*)&As[(i0 + r) * DH + j0] = hv;
    }
    // load U2 into Ws
    #pragma unroll
    for (int it = 0; it < 4; it++) {
        int q = it * 256 + t;
        int k = q >> 4, j4 = (q & 15) * 4;
        *(float4*)&Ws[k * DH + j4] = *(const float4*)&u2[k * DH + j4];
    }
    __syncthreads();

    float acc2[8][4];
    #pragma unroll
    for (int r = 0; r < 8; r++) {
        acc2[r][0] = b2s[j0 + 0]; acc2[r][1] = b2s[j0 + 1];
        acc2[r][2] = b2s[j0 + 2]; acc2[r][3] = b2s[j0 + 3];
    }
    #pragma unroll 4
    for (int k = 0; k < 64; k++) {
        float4 w = *(const float4*)&Ws[k * DH + j0];
        #pragma unroll
        for (int r = 0; r < 8; r++) {
            float a = As[(i0 + r) * DH + k];
            acc2[r][0] += a * w.x; acc2[r][1] += a * w.y;
            acc2[r][2] += a * w.z; acc2[r][3] += a * w.w;
        }
    }
    #pragma unroll
    for (int r = 0; r < 8; r++) {
        int i = base + i0 + r;
        if (i < n) {
            float4 hv;
            hv.x = fmaxf(acc2[r][0], 0.f); hv.y = fmaxf(acc2[r][1], 0.f);
            hv.z = fmaxf(acc2[r][2], 0.f); hv.w = fmaxf(acc2[r][3], 0.f);
            *(float4*)&g_h[i * DH + j0] = hv;
        }
    }
}

// =====================================================================
// Output: out = h @ out_w + out_b   ([N,64] @ [64,128])
// 256 threads, tile 64 rows x 128 cols
// =====================================================================
__global__ void k_out(const float* __restrict__ ow, const float* __restrict__ ob,
                      float* __restrict__ out, int n) {
    extern __shared__ float sm[];
    float* As = sm;            // [64][64]
    float* Ws = sm + 64 * DH;  // [64][128]
    int t = threadIdx.x;
    int base = blockIdx.x * 64;

    #pragma unroll
    for (int it = 0; it < 4; it++) {
        int q = it * 256 + t;
        int i = q >> 4, j4 = (q & 15) * 4;
        float4 v = make_float4(0.f, 0.f, 0.f, 0.f);
        if (base + i < n) v = *(const float4*)&g_h[(base + i) * DH + j4];
        *(float4*)&As[i * DH + j4] = v;
    }
    #pragma unroll
    for (int it = 0; it < 8; it++) {
        int q = it * 256 + t;
        int k = q >> 5, j4 = (q & 31) * 4;
        *(float4*)&Ws[k * 128 + j4] = *(const float4*)&ow[k * 128 + j4];
    }
    __syncthreads();

    int tx = t & 31, ty = t >> 5;
    int j0 = tx * 4, i0 = ty * 8;
    float acc[8][4];
    #pragma unroll
    for (int r = 0; r < 8; r++) {
        acc[r][0] = ob[j0 + 0]; acc[r][1] = ob[j0 + 1];
        acc[r][2] = ob[j0 + 2]; acc[r][3] = ob[j0 + 3];
    }
    #pragma unroll 4
    for (int k = 0; k < 64; k++) {
        float4 w = *(const float4*)&Ws[k * 128 + j0];
        #pragma unroll
        for (int r = 0; r < 8; r++) {
            float a = As[(i0 + r) * DH + k];
            acc[r][0] += a * w.x; acc[r][1] += a * w.y;
            acc[r][2] += a * w.z; acc[r][3] += a * w.w;
        }
    }
    #pragma unroll
    for (int r = 0; r < 8; r++) {
        int i = base + i0 + r;
        if (i < n)
            *(float4*)&out[i * 128 + j0] =
                make_float4(acc[r][0], acc[r][1], acc[r][2], acc[r][3]);
    }
}

// =====================================================================
// Launcher
// =====================================================================
extern "C" void kernel_launch(void* const* d_in, const int* in_sizes, int n_in,
                              void* d_out, int out_size) {
    const float* x      = (const float*)d_in[0];
    const int*   ei     = (const int*)  d_in[1];
    const float* in_w   = (const float*)d_in[2];
    const float* in_b   = (const float*)d_in[3];
    const float* msg_w1 = (const float*)d_in[4];
    const float* msg_b1 = (const float*)d_in[5];
    const float* msg_w2 = (const float*)d_in[6];
    const float* msg_b2 = (const float*)d_in[7];
    const float* upd_w1 = (const float*)d_in[8];
    const float* upd_b1 = (const float*)d_in[9];
    const float* upd_w2 = (const float*)d_in[10];
    const float* upd_b2 = (const float*)d_in[11];
    const float* out_w  = (const float*)d_in[12];
    const float* out_b  = (const float*)d_in[13];

    int n = in_sizes[0] / 3;
    int e = in_sizes[1] / 2;
    const int* row = ei;
    const int* col = ei + e;

    const int SMEM_PQ   = (128 * DH + 64 * DH) * 4;            // 49152
    const int SMEM_EDGE = (128 * DH + 64 * DH + 128) * 4 + 512; // 50176
    const int SMEM_UPD  = (128 * DH + 64 * DH + 128) * 4;       // 49664
    const int SMEM_OUT  = (64 * DH + 64 * 128) * 4;             // 49152

    cudaFuncSetAttribute(k_pq,     cudaFuncAttributeMaxDynamicSharedMemorySize, SMEM_PQ);
    cudaFuncSetAttribute(k_edge,   cudaFuncAttributeMaxDynamicSharedMemorySize, SMEM_EDGE);
    cudaFuncSetAttribute(k_update, cudaFuncAttributeMaxDynamicSharedMemorySize, SMEM_UPD);
    cudaFuncSetAttribute(k_out,    cudaFuncAttributeMaxDynamicSharedMemorySize, SMEM_OUT);

    k_input<<<(n * DH + 255) / 256, 256>>>(x, in_w, in_b, n);

    int nb = (n + 127) / 128;
    int eb = (e + 127) / 128;
    for (int l = 0; l < 3; l++) {
        k_pq<<<nb, 256, SMEM_PQ>>>(msg_w1 + l * 2 * DH * DH, n);
        k_zero_agg<<<(NN * DH + 255) / 256, 256>>>();
        k_edge<<<eb, 256, SMEM_EDGE>>>(row, col, msg_b1 + l * DH,
                                       msg_w2 + l * DH * DH, msg_b2 + l * DH, e);
        k_update<<<nb, 256, SMEM_UPD>>>(upd_w1 + l * 2 * DH * DH, upd_b1 + l * DH,
                                        upd_w2 + l * DH * DH, upd_b2 + l * DH, n);
    }
    k_out<<<(n + 63) / 64, 256, SMEM_OUT>>>(out_w, out_b, (float*)d_out, n);
}

// round 3
// speedup vs baseline: 1.0862x; 1.0862x over previous
#include <cuda_runtime.h>

#define NN 50000
#define EE 800000
#define DH 64

// ---- scratch (device globals; no allocation allowed) ----
__device__ float g_h[NN * DH];
__device__ float g_P[NN * DH];
__device__ float g_Q[NN * DH];
__device__ float g_agg[NN * DH];

// =====================================================================
// Input projection: h = x @ in_w + in_b   ([N,3] @ [3,64])
// =====================================================================
__global__ void k_input(const float* __restrict__ x, const float* __restrict__ w,
                        const float* __restrict__ b, int n) {
    int t = blockIdx.x * blockDim.x + threadIdx.x;
    if (t >= n * DH) return;
    int i = t / DH, j = t % DH;
    float x0 = x[i * 3 + 0], x1 = x[i * 3 + 1], x2 = x[i * 3 + 2];
    g_h[t] = x0 * w[0 * DH + j] + x1 * w[1 * DH + j] + x2 * w[2 * DH + j] + b[j];
}

// =====================================================================
// Zero the aggregation buffer (float4)
// =====================================================================
__global__ void k_zero_agg() {
    int t = blockIdx.x * blockDim.x + threadIdx.x;
    if (t < NN * DH / 4)
        *(float4*)&g_agg[t * 4] = make_float4(0.f, 0.f, 0.f, 0.f);
}

// ---- shared inner-product macro: 8x4 micro-tile, float4 over k ----
// As rows stride DH, Ws rows stride WS. acc[8][4] accumulated in place.
#define GEMM_8x4(AS, I0, WS_PTR, WSTRIDE, ACC)                                  \
    _Pragma("unroll 4")                                                          \
    for (int k0 = 0; k0 < 64; k0 += 4) {                                         \
        float4 w0 = *(const float4*)&(WS_PTR)[(k0 + 0) * (WSTRIDE) + j0];        \
        float4 w1 = *(const float4*)&(WS_PTR)[(k0 + 1) * (WSTRIDE) + j0];        \
        float4 w2 = *(const float4*)&(WS_PTR)[(k0 + 2) * (WSTRIDE) + j0];        \
        float4 w3 = *(const float4*)&(WS_PTR)[(k0 + 3) * (WSTRIDE) + j0];        \
        _Pragma("unroll")                                                        \
        for (int r = 0; r < 8; r++) {                                            \
            float4 a4 = *(const float4*)&(AS)[((I0) + r) * DH + k0];             \
            ACC[r][0] = fmaf(a4.x, w0.x, ACC[r][0]);                             \
            ACC[r][1] = fmaf(a4.x, w0.y, ACC[r][1]);                             \
            ACC[r][2] = fmaf(a4.x, w0.z, ACC[r][2]);                             \
            ACC[r][3] = fmaf(a4.x, w0.w, ACC[r][3]);                             \
            ACC[r][0] = fmaf(a4.y, w1.x, ACC[r][0]);                             \
            ACC[r][1] = fmaf(a4.y, w1.y, ACC[r][1]);                             \
            ACC[r][2] = fmaf(a4.y, w1.z, ACC[r][2]);                             \
            ACC[r][3] = fmaf(a4.y, w1.w, ACC[r][3]);                             \
            ACC[r][0] = fmaf(a4.z, w2.x, ACC[r][0]);                             \
            ACC[r][1] = fmaf(a4.z, w2.y, ACC[r][1]);                             \
            ACC[r][2] = fmaf(a4.z, w2.z, ACC[r][2]);                             \
            ACC[r][3] = fmaf(a4.z, w2.w, ACC[r][3]);                             \
            ACC[r][0] = fmaf(a4.w, w3.x, ACC[r][0]);                             \
            ACC[r][1] = fmaf(a4.w, w3.y, ACC[r][1]);                             \
            ACC[r][2] = fmaf(a4.w, w3.z, ACC[r][2]);                             \
            ACC[r][3] = fmaf(a4.w, w3.w, ACC[r][3]);                             \
        }                                                                        \
    }

// =====================================================================
// P = h @ W1[:64], Q = h @ W1[64:]   (dual GEMM, no bias)
// =====================================================================
__global__ void __launch_bounds__(256, 4)
k_pq(const float* __restrict__ w1, int n) {
    extern __shared__ float sm[];
    float* As = sm;             // [128][64]
    float* Ws = sm + 128 * DH;  // [64][64]
    int t = threadIdx.x;
    int base = blockIdx.x * 128;

    #pragma unroll
    for (int it = 0; it < 8; it++) {
        int q = it * 256 + t;
        int i = q >> 4, j4 = (q & 15) * 4;
        float4 v = make_float4(0.f, 0.f, 0.f, 0.f);
        if (base + i < n) v = *(const float4*)&g_h[(base + i) * DH + j4];
        *(float4*)&As[i * DH + j4] = v;
    }

    int tx = t & 15, ty = t >> 4;
    int j0 = tx * 4, i0 = ty * 8;

    for (int pass = 0; pass < 2; pass++) {
        __syncthreads();
        const float* wsrc = w1 + pass * 64 * DH;
        #pragma unroll
        for (int it = 0; it < 4; it++) {
            int q = it * 256 + t;
            int k = q >> 4, j4 = (q & 15) * 4;
            *(float4*)&Ws[k * DH + j4] = *(const float4*)&wsrc[k * DH + j4];
        }
        __syncthreads();

        float acc[8][4];
        #pragma unroll
        for (int r = 0; r < 8; r++)
            #pragma unroll
            for (int c = 0; c < 4; c++) acc[r][c] = 0.f;

        GEMM_8x4(As, i0, Ws, DH, acc)

        float* dst = (pass == 0) ? g_P : g_Q;
        #pragma unroll
        for (int r = 0; r < 8; r++) {
            int i = base + i0 + r;
            if (i < n)
                *(float4*)&dst[i * DH + j0] =
                    make_float4(acc[r][0], acc[r][1], acc[r][2], acc[r][3]);
        }
    }
}

// =====================================================================
// Edge kernel (dominant): hid = relu(P[row] + Q[col] + b1);
//                         m = hid @ W2 + b2; atomicAdd into agg[col]
// =====================================================================
__global__ void __launch_bounds__(256, 4)
k_edge(const int* __restrict__ row, const int* __restrict__ col,
       const float* __restrict__ b1, const float* __restrict__ w2,
       const float* __restrict__ b2, int e_total) {
    extern __shared__ float sm[];
    float* hid = sm;                 // [128][64]
    float* Ws  = sm + 128 * DH;      // [64][64]
    float* b2s = Ws + 64 * DH;       // [64]
    float* b1s = b2s + 64;           // [64]
    int*   cls = (int*)(b1s + 64);   // [128]
    int t = threadIdx.x;
    int base = blockIdx.x * 128;

    if (t < 64) { b2s[t] = b2[t]; b1s[t] = b1[t]; }
    if (t < 128) cls[t] = (base + t < e_total) ? col[base + t] : 0;

    #pragma unroll
    for (int it = 0; it < 4; it++) {
        int q = it * 256 + t;
        int k = q >> 4, j4 = (q & 15) * 4;
        *(float4*)&Ws[k * DH + j4] = *(const float4*)&w2[k * DH + j4];
    }
    __syncthreads();

    // stage 1: gather + add + bias + relu -> hid
    #pragma unroll
    for (int it = 0; it < 8; it++) {
        int q = it * 256 + t;
        int e = q >> 4, j4 = (q & 15) * 4;
        int ge = base + e;
        float4 hv = make_float4(0.f, 0.f, 0.f, 0.f);
        if (ge < e_total) {
            int rr = row[ge], cc = cls[e];
            float4 p  = *(const float4*)&g_P[rr * DH + j4];
            float4 qv = *(const float4*)&g_Q[cc * DH + j4];
            hv.x = fmaxf(p.x + qv.x + b1s[j4 + 0], 0.f);
            hv.y = fmaxf(p.y + qv.y + b1s[j4 + 1], 0.f);
            hv.z = fmaxf(p.z + qv.z + b1s[j4 + 2], 0.f);
            hv.w = fmaxf(p.w + qv.w + b1s[j4 + 3], 0.f);
        }
        *(float4*)&hid[e * DH + j4] = hv;
    }
    __syncthreads();

    int tx = t & 15, ty = t >> 4;
    int j0 = tx * 4, e0 = ty * 8;
    float acc[8][4];
    #pragma unroll
    for (int r = 0; r < 8; r++) {
        acc[r][0] = b2s[j0 + 0]; acc[r][1] = b2s[j0 + 1];
        acc[r][2] = b2s[j0 + 2]; acc[r][3] = b2s[j0 + 3];
    }

    GEMM_8x4(hid, e0, Ws, DH, acc)

    // scatter-add
    #pragma unroll
    for (int r = 0; r < 8; r++) {
        int ge = base + e0 + r;
        if (ge < e_total) {
            float* dst = &g_agg[cls[e0 + r] * DH + j0];
            atomicAdd(dst + 0, acc[r][0]);
            atomicAdd(dst + 1, acc[r][1]);
            atomicAdd(dst + 2, acc[r][2]);
            atomicAdd(dst + 3, acc[r][3]);
        }
    }
}

// =====================================================================
// Node update: h = relu( relu(h@U1a + agg@U1b + b1) @ U2 + b2 )   (in place)
// =====================================================================
__global__ void __launch_bounds__(256, 4)
k_update(const float* __restrict__ u1, const float* __restrict__ ub1,
         const float* __restrict__ u2, const float* __restrict__ ub2,
         int n) {
    extern __shared__ float sm[];
    float* As  = sm;             // [128][64]
    float* Ws  = sm + 128 * DH;  // [64][64]
    float* b1s = Ws + 64 * DH;
    float* b2s = b1s + 64;
    int t = threadIdx.x;
    int base = blockIdx.x * 128;
    if (t < 64) { b1s[t] = ub1[t]; b2s[t] = ub2[t]; }

    int tx = t & 15, ty = t >> 4;
    int j0 = tx * 4, i0 = ty * 8;

    float acc[8][4];
    #pragma unroll
    for (int r = 0; r < 8; r++)
        #pragma unroll
        for (int c = 0; c < 4; c++) acc[r][c] = 0.f;

    for (int pass = 0; pass < 2; pass++) {
        __syncthreads();
        const float* a_src = (pass == 0) ? g_h : g_agg;
        #pragma unroll
        for (int it = 0; it < 8; it++) {
            int q = it * 256 + t;
            int i = q >> 4, j4 = (q & 15) * 4;
            float4 v = make_float4(0.f, 0.f, 0.f, 0.f);
            if (base + i < n) v = *(const float4*)&a_src[(base + i) * DH + j4];
            *(float4*)&As[i * DH + j4] = v;
        }
        const float* wsrc = u1 + pass * 64 * DH;
        #pragma unroll
        for (int it = 0; it < 4; it++) {
            int q = it * 256 + t;
            int k = q >> 4, j4 = (q & 15) * 4;
            *(float4*)&Ws[k * DH + j4] = *(const float4*)&wsrc[k * DH + j4];
        }
        __syncthreads();

        GEMM_8x4(As, i0, Ws, DH, acc)
    }
    __syncthreads();

    // hid = relu(acc + b1) -> As
    #pragma unroll
    for (int r = 0; r < 8; r++) {
        float4 hv;
        hv.x = fmaxf(acc[r][0] + b1s[j0 + 0], 0.f);
        hv.y = fmaxf(acc[r][1] + b1s[j0 + 1], 0.f);
        hv.z = fmaxf(acc[r][2] + b1s[j0 + 2], 0.f);
        hv.w = fmaxf(acc[r][3] + b1s[j0 + 3], 0.f);
        *(float4*)&As[(i0 + r) * DH + j0] = hv;
    }
    // load U2 into Ws
    #pragma unroll
    for (int it = 0; it < 4; it++) {
        int q = it * 256 + t;
        int k = q >> 4, j4 = (q & 15) * 4;
        *(float4*)&Ws[k * DH + j4] = *(const float4*)&u2[k * DH + j4];
    }
    __syncthreads();

    float acc2[8][4];
    #pragma unroll
    for (int r = 0; r < 8; r++) {
        acc2[r][0] = b2s[j0 + 0]; acc2[r][1] = b2s[j0 + 1];
        acc2[r][2] = b2s[j0 + 2]; acc2[r][3] = b2s[j0 + 3];
    }

    GEMM_8x4(As, i0, Ws, DH, acc2)

    #pragma unroll
    for (int r = 0; r < 8; r++) {
        int i = base + i0 + r;
        if (i < n) {
            float4 hv;
            hv.x = fmaxf(acc2[r][0], 0.f); hv.y = fmaxf(acc2[r][1], 0.f);
            hv.z = fmaxf(acc2[r][2], 0.f); hv.w = fmaxf(acc2[r][3], 0.f);
            *(float4*)&g_h[i * DH + j0] = hv;
        }
    }
}

// =====================================================================
// Output: out = h @ out_w + out_b   ([N,64] @ [64,128])
// =====================================================================
__global__ void __launch_bounds__(256, 4)
k_out(const float* __restrict__ ow, const float* __restrict__ ob,
      float* __restrict__ out, int n) {
    extern __shared__ float sm[];
    float* As = sm;            // [64][64]
    float* Ws = sm + 64 * DH;  // [64][128]
    int t = threadIdx.x;
    int base = blockIdx.x * 64;

    #pragma unroll
    for (int it = 0; it < 4; it++) {
        int q = it * 256 + t;
        int i = q >> 4, j4 = (q & 15) * 4;
        float4 v = make_float4(0.f, 0.f, 0.f, 0.f);
        if (base + i < n) v = *(const float4*)&g_h[(base + i) * DH + j4];
        *(float4*)&As[i * DH + j4] = v;
    }
    #pragma unroll
    for (int it = 0; it < 8; it++) {
        int q = it * 256 + t;
        int k = q >> 5, j4 = (q & 31) * 4;
        *(float4*)&Ws[k * 128 + j4] = *(const float4*)&ow[k * 128 + j4];
    }
    __syncthreads();

    int tx = t & 31, ty = t >> 5;
    int j0 = tx * 4, i0 = ty * 8;
    float acc[8][4];
    #pragma unroll
    for (int r = 0; r < 8; r++) {
        acc[r][0] = ob[j0 + 0]; acc[r][1] = ob[j0 + 1];
        acc[r][2] = ob[j0 + 2]; acc[r][3] = ob[j0 + 3];
    }

    GEMM_8x4(As, i0, Ws, 128, acc)

    #pragma unroll
    for (int r = 0; r < 8; r++) {
        int i = base + i0 + r;
        if (i < n)
            *(float4*)&out[i * 128 + j0] =
                make_float4(acc[r][0], acc[r][1], acc[r][2], acc[r][3]);
    }
}

// =====================================================================
// Launcher
// =====================================================================
extern "C" void kernel_launch(void* const* d_in, const int* in_sizes, int n_in,
                              void* d_out, int out_size) {
    const float* x      = (const float*)d_in[0];
    const int*   ei     = (const int*)  d_in[1];
    const float* in_w   = (const float*)d_in[2];
    const float* in_b   = (const float*)d_in[3];
    const float* msg_w1 = (const float*)d_in[4];
    const float* msg_b1 = (const float*)d_in[5];
    const float* msg_w2 = (const float*)d_in[6];
    const float* msg_b2 = (const float*)d_in[7];
    const float* upd_w1 = (const float*)d_in[8];
    const float* upd_b1 = (const float*)d_in[9];
    const float* upd_w2 = (const float*)d_in[10];
    const float* upd_b2 = (const float*)d_in[11];
    const float* out_w  = (const float*)d_in[12];
    const float* out_b  = (const float*)d_in[13];

    int n = in_sizes[0] / 3;
    int e = in_sizes[1] / 2;
    const int* row = ei;
    const int* col = ei + e;

    const int SMEM_PQ   = (128 * DH + 64 * DH) * 4;             // 49152
    const int SMEM_EDGE = (128 * DH + 64 * DH + 128) * 4 + 512; // 50176
    const int SMEM_UPD  = (128 * DH + 64 * DH + 128) * 4;       // 49664
    const int SMEM_OUT  = (64 * DH + 64 * 128) * 4;             // 49152

    cudaFuncSetAttribute(k_pq,     cudaFuncAttributeMaxDynamicSharedMemorySize, SMEM_PQ);
    cudaFuncSetAttribute(k_edge,   cudaFuncAttributeMaxDynamicSharedMemorySize, SMEM_EDGE);
    cudaFuncSetAttribute(k_update, cudaFuncAttributeMaxDynamicSharedMemorySize, SMEM_UPD);
    cudaFuncSetAttribute(k_out,    cudaFuncAttributeMaxDynamicSharedMemorySize, SMEM_OUT);

    k_input<<<(n * DH + 255) / 256, 256>>>(x, in_w, in_b, n);

    int nb = (n + 127) / 128;
    int eb = (e + 127) / 128;
    for (int l = 0; l < 3; l++) {
        k_pq<<<nb, 256, SMEM_PQ>>>(msg_w1 + l * 2 * DH * DH, n);
        k_zero_agg<<<(NN * DH / 4 + 255) / 256, 256>>>();
        k_edge<<<eb, 256, SMEM_EDGE>>>(row, col, msg_b1 + l * DH,
                                       msg_w2 + l * DH * DH, msg_b2 + l * DH, e);
        k_update<<<nb, 256, SMEM_UPD>>>(upd_w1 + l * 2 * DH * DH, upd_b1 + l * DH,
                                        upd_w2 + l * DH * DH, upd_b2 + l * DH, n);
    }
    k_out<<<(n + 63) / 64, 256, SMEM_OUT>>>(out_w, out_b, (float*)d_out, n);
}

// round 4
// speedup vs baseline: 2.2793x; 2.0985x over previous
#include <cuda_runtime.h>

#define NN 50000
#define EE 800000
#define DH 64

// ---- scratch (device globals; no allocation allowed) ----
__device__ float g_h[NN * DH];
__device__ float g_P[NN * DH];
__device__ float g_Q[NN * DH];
__device__ float g_aggH[NN * DH];   // sum of relu hiddens per dst node
__device__ float g_deg[NN];         // in-degree (as float)
__device__ float g_W2U[DH * DH];    // W2 @ U1b  (per layer, recomputed)
__device__ float g_b2U[DH];         // b2 @ U1b

// =====================================================================
// Input projection: h = x @ in_w + in_b   ([N,3] @ [3,64])
// =====================================================================
__global__ void k_input(const float* __restrict__ x, const float* __restrict__ w,
                        const float* __restrict__ b, int n) {
    int t = blockIdx.x * blockDim.x + threadIdx.x;
    if (t >= n * DH) return;
    int i = t / DH, j = t % DH;
    float x0 = x[i * 3 + 0], x1 = x[i * 3 + 1], x2 = x[i * 3 + 2];
    g_h[t] = x0 * w[0 * DH + j] + x1 * w[1 * DH + j] + x2 * w[2 * DH + j] + b[j];
}

// =====================================================================
// Zero helpers
// =====================================================================
__global__ void k_zero_agg() {
    int t = blockIdx.x * blockDim.x + threadIdx.x;
    if (t < NN * DH / 4)
        *(float4*)&g_aggH[t * 4] = make_float4(0.f, 0.f, 0.f, 0.f);
}
__global__ void k_zero_deg() {
    int t = blockIdx.x * blockDim.x + threadIdx.x;
    if (t < NN) g_deg[t] = 0.f;
}
__global__ void k_deg(const int* __restrict__ col, int e) {
    int ge = blockIdx.x * blockDim.x + threadIdx.x;
    if (ge < e) atomicAdd(&g_deg[col[ge]], 1.0f);
}

// =====================================================================
// Per-layer precompute: W2U = W2 @ U1b, b2U = b2 @ U1b (single block)
// U1b = rows [64:128) of upd_w1[l]  ([2*DH, DH])
// =====================================================================
__global__ void k_prep(const float* __restrict__ w2, const float* __restrict__ u1b,
                       const float* __restrict__ b2) {
    __shared__ float W2s[DH * DH];
    __shared__ float U1s[DH * DH];
    __shared__ float b2s[DH];
    int t = threadIdx.x;
    for (int q = t; q < DH * DH / 4; q += 256) {
        *(float4*)&W2s[q * 4] = *(const float4*)&w2[q * 4];
        *(float4*)&U1s[q * 4] = *(const float4*)&u1b[q * 4];
    }
    if (t < DH) b2s[t] = b2[t];
    __syncthreads();
    for (int idx = t; idx < DH * DH; idx += 256) {
        int k = idx >> 6, j = idx & 63;
        float s = 0.f;
        #pragma unroll 8
        for (int m = 0; m < DH; m++) s = fmaf(W2s[k * DH + m], U1s[m * DH + j], s);
        g_W2U[idx] = s;
    }
    if (t < DH) {
        float s = 0.f;
        #pragma unroll 8
        for (int m = 0; m < DH; m++) s = fmaf(b2s[m], U1s[m * DH + t], s);
        g_b2U[t] = s;
    }
}

// ---- shared inner-product macro: 8x4 micro-tile, float4 over k ----
#define GEMM_8x4(AS, I0, WS_PTR, WSTRIDE, ACC)                                  \
    _Pragma("unroll 4")                                                          \
    for (int k0 = 0; k0 < 64; k0 += 4) {                                         \
        float4 w0 = *(const float4*)&(WS_PTR)[(k0 + 0) * (WSTRIDE) + j0];        \
        float4 w1 = *(const float4*)&(WS_PTR)[(k0 + 1) * (WSTRIDE) + j0];        \
        float4 w2 = *(const float4*)&(WS_PTR)[(k0 + 2) * (WSTRIDE) + j0];        \
        float4 w3 = *(const float4*)&(WS_PTR)[(k0 + 3) * (WSTRIDE) + j0];        \
        _Pragma("unroll")                                                        \
        for (int r = 0; r < 8; r++) {                                            \
            float4 a4 = *(const float4*)&(AS)[((I0) + r) * DH + k0];             \
            ACC[r][0] = fmaf(a4.x, w0.x, ACC[r][0]);                             \
            ACC[r][1] = fmaf(a4.x, w0.y, ACC[r][1]);                             \
            ACC[r][2] = fmaf(a4.x, w0.z, ACC[r][2]);                             \
            ACC[r][3] = fmaf(a4.x, w0.w, ACC[r][3]);                             \
            ACC[r][0] = fmaf(a4.y, w1.x, ACC[r][0]);                             \
            ACC[r][1] = fmaf(a4.y, w1.y, ACC[r][1]);                             \
            ACC[r][2] = fmaf(a4.y, w1.z, ACC[r][2]);                             \
            ACC[r][3] = fmaf(a4.y, w1.w, ACC[r][3]);                             \
            ACC[r][0] = fmaf(a4.z, w2.x, ACC[r][0]);                             \
            ACC[r][1] = fmaf(a4.z, w2.y, ACC[r][1]);                             \
            ACC[r][2] = fmaf(a4.z, w2.z, ACC[r][2]);                             \
            ACC[r][3] = fmaf(a4.z, w2.w, ACC[r][3]);                             \
            ACC[r][0] = fmaf(a4.w, w3.x, ACC[r][0]);                             \
            ACC[r][1] = fmaf(a4.w, w3.y, ACC[r][1]);                             \
            ACC[r][2] = fmaf(a4.w, w3.z, ACC[r][2]);                             \
            ACC[r][3] = fmaf(a4.w, w3.w, ACC[r][3]);                             \
        }                                                                        \
    }

// =====================================================================
// P = h @ W1[:64], Q = h @ W1[64:]   (dual GEMM, no bias)
// =====================================================================
__global__ void __launch_bounds__(256, 4)
k_pq(const float* __restrict__ w1, int n) {
    extern __shared__ float sm[];
    float* As = sm;             // [128][64]
    float* Ws = sm + 128 * DH;  // [64][64]
    int t = threadIdx.x;
    int base = blockIdx.x * 128;

    #pragma unroll
    for (int it = 0; it < 8; it++) {
        int q = it * 256 + t;
        int i = q >> 4, j4 = (q & 15) * 4;
        float4 v = make_float4(0.f, 0.f, 0.f, 0.f);
        if (base + i < n) v = *(const float4*)&g_h[(base + i) * DH + j4];
        *(float4*)&As[i * DH + j4] = v;
    }

    int tx = t & 15, ty = t >> 4;
    int j0 = tx * 4, i0 = ty * 8;

    for (int pass = 0; pass < 2; pass++) {
        __syncthreads();
        const float* wsrc = w1 + pass * 64 * DH;
        #pragma unroll
        for (int it = 0; it < 4; it++) {
            int q = it * 256 + t;
            int k = q >> 4, j4 = (q & 15) * 4;
            *(float4*)&Ws[k * DH + j4] = *(const float4*)&wsrc[k * DH + j4];
        }
        __syncthreads();

        float acc[8][4];
        #pragma unroll
        for (int r = 0; r < 8; r++)
            #pragma unroll
            for (int c = 0; c < 4; c++) acc[r][c] = 0.f;

        GEMM_8x4(As, i0, Ws, DH, acc)

        float* dst = (pass == 0) ? g_P : g_Q;
        #pragma unroll
        for (int r = 0; r < 8; r++) {
            int i = base + i0 + r;
            if (i < n)
                *(float4*)&dst[i * DH + j0] =
                    make_float4(acc[r][0], acc[r][1], acc[r][2], acc[r][3]);
        }
    }
}

// =====================================================================
// Edge kernel (new, GEMM-free): hid = relu(P[row] + Q[col] + b1);
// vector red into aggH[col]. One thread per (edge, 4 features).
// =====================================================================
__global__ void __launch_bounds__(256)
k_edge_lite(const int* __restrict__ row, const int* __restrict__ col,
            const float* __restrict__ b1, int e_total) {
    int idx = blockIdx.x * blockDim.x + threadIdx.x;
    int ge = idx >> 4;
    if (ge >= e_total) return;
    int j4 = (idx & 15) << 2;
    int rr = __ldg(&row[ge]);
    int cc = __ldg(&col[ge]);
    float4 p  = *(const float4*)&g_P[rr * DH + j4];
    float4 qv = *(const float4*)&g_Q[cc * DH + j4];
    float4 b  = *(const float4*)&b1[j4];
    float hx = fmaxf(p.x + qv.x + b.x, 0.f);
    float hy = fmaxf(p.y + qv.y + b.y, 0.f);
    float hz = fmaxf(p.z + qv.z + b.z, 0.f);
    float hw = fmaxf(p.w + qv.w + b.w, 0.f);
    float* dst = &g_aggH[cc * DH + j4];
    asm volatile("red.global.add.v4.f32 [%0], {%1, %2, %3, %4};"
                 :: "l"(dst), "f"(hx), "f"(hy), "f"(hz), "f"(hw) : "memory");
}

// =====================================================================
// Node update:
//   pre  = h@U1a + aggH@W2U + deg*b2U + ub1
//   h    = relu( relu(pre) @ U2 + ub2 )
// =====================================================================
__global__ void __launch_bounds__(256, 4)
k_update(const float* __restrict__ u1a, const float* __restrict__ ub1,
         const float* __restrict__ u2, const float* __restrict__ ub2,
         int n) {
    extern __shared__ float sm[];
    float* As   = sm;             // [128][64]
    float* Ws   = sm + 128 * DH;  // [64][64]
    float* b1s  = Ws + 64 * DH;   // ub1
    float* b2s  = b1s + 64;       // ub2
    float* b2Us = b2s + 64;       // b2U
    int t = threadIdx.x;
    int base = blockIdx.x * 128;
    if (t < 64) { b1s[t] = ub1[t]; b2s[t] = ub2[t]; b2Us[t] = g_b2U[t]; }

    int tx = t & 15, ty = t >> 4;
    int j0 = tx * 4, i0 = ty * 8;

    float acc[8][4];
    #pragma unroll
    for (int r = 0; r < 8; r++)
        #pragma unroll
        for (int c = 0; c < 4; c++) acc[r][c] = 0.f;

    for (int pass = 0; pass < 2; pass++) {
        __syncthreads();
        const float* a_src = (pass == 0) ? g_h : g_aggH;
        const float* wsrc  = (pass == 0) ? u1a : g_W2U;
        #pragma unroll
        for (int it = 0; it < 8; it++) {
            int q = it * 256 + t;
            int i = q >> 4, j4 = (q & 15) * 4;
            float4 v = make_float4(0.f, 0.f, 0.f, 0.f);
            if (base + i < n) v = *(const float4*)&a_src[(base + i) * DH + j4];
            *(float4*)&As[i * DH + j4] = v;
        }
        #pragma unroll
        for (int it = 0; it < 4; it++) {
            int q = it * 256 + t;
            int k = q >> 4, j4 = (q & 15) * 4;
            *(float4*)&Ws[k * DH + j4] = *(const float4*)&wsrc[k * DH + j4];
        }
        __syncthreads();

        GEMM_8x4(As, i0, Ws, DH, acc)
    }
    __syncthreads();

    // hid = relu(acc + deg*b2U + ub1) -> As
    #pragma unroll
    for (int r = 0; r < 8; r++) {
        int i = base + i0 + r;
        float dg = (i < n) ? g_deg[i] : 0.f;
        float4 hv;
        hv.x = fmaxf(fmaf(dg, b2Us[j0 + 0], acc[r][0]) + b1s[j0 + 0], 0.f);
        hv.y = fmaxf(fmaf(dg, b2Us[j0 + 1], acc[r][1]) + b1s[j0 + 1], 0.f);
        hv.z = fmaxf(fmaf(dg, b2Us[j0 + 2], acc[r][2]) + b1s[j0 + 2], 0.f);
        hv.w = fmaxf(fmaf(dg, b2Us[j0 + 3], acc[r][3]) + b1s[j0 + 3], 0.f);
        *(float4*)&As[(i0 + r) * DH + j0] = hv;
    }
    // load U2 into Ws
    #pragma unroll
    for (int it = 0; it < 4; it++) {
        int q = it * 256 + t;
        int k = q >> 4, j4 = (q & 15) * 4;
        *(float4*)&Ws[k * DH + j4] = *(const float4*)&u2[k * DH + j4];
    }
    __syncthreads();

    float acc2[8][4];
    #pragma unroll
    for (int r = 0; r < 8; r++) {
        acc2[r][0] = b2s[j0 + 0]; acc2[r][1] = b2s[j0 + 1];
        acc2[r][2] = b2s[j0 + 2]; acc2[r][3] = b2s[j0 + 3];
    }

    GEMM_8x4(As, i0, Ws, DH, acc2)

    #pragma unroll
    for (int r = 0; r < 8; r++) {
        int i = base + i0 + r;
        if (i < n) {
            float4 hv;
            hv.x = fmaxf(acc2[r][0], 0.f); hv.y = fmaxf(acc2[r][1], 0.f);
            hv.z = fmaxf(acc2[r][2], 0.f); hv.w = fmaxf(acc2[r][3], 0.f);
            *(float4*)&g_h[i * DH + j0] = hv;
        }
    }
}

// =====================================================================
// Output: out = h @ out_w + out_b   ([N,64] @ [64,128])
// =====================================================================
__global__ void __launch_bounds__(256, 4)
k_out(const float* __restrict__ ow, const float* __restrict__ ob,
      float* __restrict__ out, int n) {
    extern __shared__ float sm[];
    float* As = sm;            // [64][64]
    float* Ws = sm + 64 * DH;  // [64][128]
    int t = threadIdx.x;
    int base = blockIdx.x * 64;

    #pragma unroll
    for (int it = 0; it < 4; it++) {
        int q = it * 256 + t;
        int i = q >> 4, j4 = (q & 15) * 4;
        float4 v = make_float4(0.f, 0.f, 0.f, 0.f);
        if (base + i < n) v = *(const float4*)&g_h[(base + i) * DH + j4];
        *(float4*)&As[i * DH + j4] = v;
    }
    #pragma unroll
    for (int it = 0; it < 8; it++) {
        int q = it * 256 + t;
        int k = q >> 5, j4 = (q & 31) * 4;
        *(float4*)&Ws[k * 128 + j4] = *(const float4*)&ow[k * 128 + j4];
    }
    __syncthreads();

    int tx = t & 31, ty = t >> 5;
    int j0 = tx * 4, i0 = ty * 8;
    float acc[8][4];
    #pragma unroll
    for (int r = 0; r < 8; r++) {
        acc[r][0] = ob[j0 + 0]; acc[r][1] = ob[j0 + 1];
        acc[r][2] = ob[j0 + 2]; acc[r][3] = ob[j0 + 3];
    }

    GEMM_8x4(As, i0, Ws, 128, acc)

    #pragma unroll
    for (int r = 0; r < 8; r++) {
        int i = base + i0 + r;
        if (i < n)
            *(float4*)&out[i * 128 + j0] =
                make_float4(acc[r][0], acc[r][1], acc[r][2], acc[r][3]);
    }
}

// =====================================================================
// Launcher
// =====================================================================
extern "C" void kernel_launch(void* const* d_in, const int* in_sizes, int n_in,
                              void* d_out, int out_size) {
    const float* x      = (const float*)d_in[0];
    const int*   ei     = (const int*)  d_in[1];
    const float* in_w   = (const float*)d_in[2];
    const float* in_b   = (const float*)d_in[3];
    const float* msg_w1 = (const float*)d_in[4];
    const float* msg_b1 = (const float*)d_in[5];
    const float* msg_w2 = (const float*)d_in[6];
    const float* msg_b2 = (const float*)d_in[7];
    const float* upd_w1 = (const float*)d_in[8];
    const float* upd_b1 = (const float*)d_in[9];
    const float* upd_w2 = (const float*)d_in[10];
    const float* upd_b2 = (const float*)d_in[11];
    const float* out_w  = (const float*)d_in[12];
    const float* out_b  = (const float*)d_in[13];

    int n = in_sizes[0] / 3;
    int e = in_sizes[1] / 2;
    const int* row = ei;
    const int* col = ei + e;

    const int SMEM_PQ  = (128 * DH + 64 * DH) * 4;           // 49152
    const int SMEM_UPD = (128 * DH + 64 * DH + 192) * 4;     // 49920
    const int SMEM_OUT = (64 * DH + 64 * 128) * 4;           // 49152

    cudaFuncSetAttribute(k_pq,     cudaFuncAttributeMaxDynamicSharedMemorySize, SMEM_PQ);
    cudaFuncSetAttribute(k_update, cudaFuncAttributeMaxDynamicSharedMemorySize, SMEM_UPD);
    cudaFuncSetAttribute(k_out,    cudaFuncAttributeMaxDynamicSharedMemorySize, SMEM_OUT);

    k_input<<<(n * DH + 255) / 256, 256>>>(x, in_w, in_b, n);
    k_zero_deg<<<(NN + 255) / 256, 256>>>();
    k_deg<<<(e + 255) / 256, 256>>>(col, e);

    int nb = (n + 127) / 128;
    int eb16 = (e * 16 + 255) / 256;
    for (int l = 0; l < 3; l++) {
        k_pq<<<nb, 256, SMEM_PQ>>>(msg_w1 + l * 2 * DH * DH, n);
        k_zero_agg<<<(NN * DH / 4 + 255) / 256, 256>>>();
        k_prep<<<1, 256>>>(msg_w2 + l * DH * DH,
                           upd_w1 + l * 2 * DH * DH + 64 * DH,
                           msg_b2 + l * DH);
        k_edge_lite<<<eb16, 256>>>(row, col, msg_b1 + l * DH, e);
        k_update<<<nb, 256, SMEM_UPD>>>(upd_w1 + l * 2 * DH * DH, upd_b1 + l * DH,
                                        upd_w2 + l * DH * DH, upd_b2 + l * DH, n);
    }
    k_out<<<(n + 63) / 64, 256, SMEM_OUT>>>(out_w, out_b, (float*)d_out, n);
}